// round 6
// baseline (speedup 1.0000x reference)
#include <cuda_runtime.h>

#define NGRID 10000
#define NSTEP 365
#define NMUL 16
#define NEARZERO 1e-5f
#define TBATCH 5            // 365 = 5 * 73, no remainder

__global__ __launch_bounds__(64)
void hbv_waterloss_kernel(
    const float* __restrict__ x,     // (365, 10000, 3) P,T,PET
    const float* __restrict__ praw,  // (365, 10000, 3, 16) -- only step 364 used
    const float* __restrict__ wraw,  // (10000, 13, 16)
    const float* __restrict__ ac,    // (10000,)
    float* __restrict__ out)         // (365, 10000)
{
    const int tid = blockIdx.x * blockDim.x + threadIdx.x;
    const int g = tid >> 4;        // grid cell
    const int m = tid & 15;        // multiplier index within grid
    if (g >= NGRID) return;

    // ---- parameter scaling (HBV params from last timestep: static_idx = -1) ----
    const float* pr = praw + ((size_t)364 * NGRID + g) * (3 * NMUL) + m;
    const float parBETA   = 1.0f  + pr[0]      * 5.0f;
    const float parK0     = 0.05f + pr[16]     * 0.85f;
    const float parBETAET = 0.3f  + pr[32]     * 4.7f;

    const float* wr = wraw + (size_t)g * (13 * NMUL) + m;
    const float parFC    = 50.0f  + wr[0]   * 950.0f;
    const float parK1    = 0.01f  + wr[16]  * 0.49f;
    const float parK2    = 0.001f + wr[32]  * 0.199f;
    const float parLP    = 0.2f   + wr[48]  * 0.8f;
    const float parPERC  =          wr[64]  * 10.0f;
    const float parUZL   =          wr[80]  * 100.0f;
    const float parTT    = -2.5f  + wr[96]  * 5.0f;
    const float parCFMAX = 0.5f   + wr[112] * 9.5f;
    const float parCFR   =          wr[128] * 0.1f;
    const float parCWH   =          wr[144] * 0.2f;
    const float parC     =          wr[160];
    const float parTR    =          wr[176] * 20.0f;
    const float parAc    =          wr[192] * 2500.0f;

    // ---- regional flow (time-invariant per (g,m)) ----
    const float acm = ac[g];
    float regional_flow;
    {
        const float rf = fminf(fmaxf((acm - parAc) * 0.001f, -1.0f), 1.0f);
        if (acm < 2500.0f) {
            regional_flow = rf * parTR;
        } else {
            const float e = fminf(fmaxf(-(acm - 2500.0f) * (1.0f / 50.0f), -10.0f), 0.0f);
            regional_flow = expf(e) * parTR;
        }
    }

    const float invFC       = 1.0f / parFC;
    const float invLPFC     = 1.0f / (parLP * parFC);
    const float negCFRCFMAX = -(parCFR * parCFMAX);
    const float oneMK1      = 1.0f - parK1;   // SUZ after Q1 = SUZ*(1-K1)
    const float oneMK2      = 1.0f - parK2;   // SLZ after Q2 = SLZ*(1-K2)

    float SNOWPACK = 0.001f, MELTWATER = 0.001f, SM = 0.001f, SUZ = 0.001f, SLZ = 0.001f;

    const float* xt = x + (size_t)g * 3;    // advances NGRID*3 per step
    float* og = out + g;                    // advances NGRID per step

    #pragma unroll 1
    for (int tb = 0; tb < NSTEP / TBATCH; ++tb) {
        float qbuf[TBATCH];

        #pragma unroll
        for (int k = 0; k < TBATCH; ++k) {
            const float Pm   = __ldg(xt + 0);
            const float Tm   = __ldg(xt + 1);
            const float PETm = __ldg(xt + 2);
            xt += NGRID * 3;

            // ---- snow routine ----
            const float dtt  = Tm - parTT;
            const float RAIN = (dtt >= 0.0f) ? Pm : 0.0f;
            SNOWPACK += Pm - RAIN;
            const float melt = fminf(fmaxf(parCFMAX * dtt, 0.0f), SNOWPACK);
            MELTWATER += melt;
            SNOWPACK  -= melt;
            const float refreezing = fminf(fmaxf(negCFRCFMAX * dtt, 0.0f), MELTWATER);
            SNOWPACK  += refreezing;
            MELTWATER -= refreezing;
            const float tosoil = fmaxf(MELTWATER - parCWH * SNOWPACK, 0.0f);
            MELTWATER -= tosoil;

            // ---- soil routine ----
            // powf of non-negative base is >= 0 -> lower clip of jnp.clip is dead
            const float soil_wetness = fminf(__powf(SM * invFC, parBETA), 1.0f);
            const float rt = RAIN + tosoil;
            const float recharge = rt * soil_wetness;
            SM += rt - recharge;
            const float excess = fmaxf(SM - parFC, 0.0f);
            SM -= excess;
            const float evapfactor = fminf(__powf(SM * invLPFC, parBETAET), 1.0f);
            // ETact fold: max(SM - min(SM, PET*ef), NZ) == max(SM - PET*ef, NZ)
            SM = fmaxf(SM - PETm * evapfactor, NEARZERO);
            // capillary: parC<=1 and (1-min(SM/FC,1))<=1 -> product <= SLZ, outer min dead
            const float capillary = (parC * SLZ) * (1.0f - fminf(SM * invFC, 1.0f));
            SM  = fmaxf(SM + capillary, NEARZERO);
            SLZ = fmaxf(SLZ - capillary, NEARZERO);

            // ---- response routine ----
            SUZ += recharge + excess;
            const float PERC = fminf(SUZ, parPERC);
            SUZ -= PERC;
            const float Q0 = parK0 * fmaxf(SUZ - parUZL, 0.0f);
            SUZ -= Q0;
            const float Q1 = parK1 * SUZ;
            SUZ *= oneMK1;                       // == SUZ - Q1
            SLZ = fmaxf(SLZ + PERC + regional_flow, 0.0f);
            const float Q2 = parK2 * SLZ;
            SLZ *= oneMK2;                       // == SLZ - Q2
            qbuf[k] = Q0 + Q1 + Q2;
        }

        // 5 independent 16-lane butterfly reductions -> shuffle latency pipelines
        #pragma unroll
        for (int k = 0; k < TBATCH; ++k) {
            float q = qbuf[k];
            q += __shfl_xor_sync(0xffffffffu, q, 8);
            q += __shfl_xor_sync(0xffffffffu, q, 4);
            q += __shfl_xor_sync(0xffffffffu, q, 2);
            q += __shfl_xor_sync(0xffffffffu, q, 1);
            qbuf[k] = q;
        }

        if (m == 0) {
            #pragma unroll
            for (int k = 0; k < TBATCH; ++k)
                og[(size_t)k * NGRID] = qbuf[k] * (1.0f / 16.0f);
        }
        og += (size_t)TBATCH * NGRID;
    }
}

extern "C" void kernel_launch(void* const* d_in, const int* in_sizes, int n_in,
                              void* d_out, int out_size) {
    const float* x  = nullptr;
    const float* pr = nullptr;
    const float* wr = nullptr;
    const float* ac = nullptr;
    for (int i = 0; i < n_in; ++i) {
        const long n = (long)in_sizes[i];
        if      (n == 365L * NGRID * 3)            x  = (const float*)d_in[i];
        else if (n == 365L * NGRID * 3 * NMUL)     pr = (const float*)d_in[i];
        else if (n == (long)NGRID * 13 * NMUL)     wr = (const float*)d_in[i];
        else if (n == (long)NGRID)                 ac = (const float*)d_in[i];
    }
    // 2-warp blocks: 2500 blocks -> 16-17 blocks (32-34 warps) per SM,
    // under the 32-block slot limit, true single wave, +0.6% max imbalance
    const int threads = 64;
    const int blocks  = (NGRID * NMUL + threads - 1) / threads;  // 2500
    hbv_waterloss_kernel<<<blocks, threads>>>(x, pr, wr, ac, (float*)d_out);
}

// round 7
// speedup vs baseline: 1.0917x; 1.0917x over previous
#include <cuda_runtime.h>

#define NGRID 10000
#define NSTEP 365
#define NMUL 16
#define NEARZERO 1e-5f
#define TBATCH 5            // 365 = 5 * 73, no remainder
#define NBATCH (NSTEP / TBATCH)
#define XSTRIDE (NGRID * 3)

__global__ __launch_bounds__(32)
void hbv_waterloss_kernel(
    const float* __restrict__ x,     // (365, 10000, 3) P,T,PET
    const float* __restrict__ praw,  // (365, 10000, 3, 16) -- only step 364 used
    const float* __restrict__ wraw,  // (10000, 13, 16)
    const float* __restrict__ ac,    // (10000,)
    float* __restrict__ out)         // (365, 10000)
{
    const int tid = blockIdx.x * blockDim.x + threadIdx.x;
    const int g = tid >> 4;        // grid cell
    const int m = tid & 15;        // multiplier index within grid
    if (g >= NGRID) return;

    // ---- parameter scaling (HBV params from last timestep: static_idx = -1) ----
    const float* pr = praw + ((size_t)364 * NGRID + g) * (3 * NMUL) + m;
    const float parBETA   = 1.0f  + pr[0]      * 5.0f;
    const float parK0     = 0.05f + pr[16]     * 0.85f;
    const float parBETAET = 0.3f  + pr[32]     * 4.7f;

    const float* wr = wraw + (size_t)g * (13 * NMUL) + m;
    const float parFC    = 50.0f  + wr[0]   * 950.0f;
    const float parK1    = 0.01f  + wr[16]  * 0.49f;
    const float parK2    = 0.001f + wr[32]  * 0.199f;
    const float parLP    = 0.2f   + wr[48]  * 0.8f;
    const float parPERC  =          wr[64]  * 10.0f;
    const float parUZL   =          wr[80]  * 100.0f;
    const float parTT    = -2.5f  + wr[96]  * 5.0f;
    const float parCFMAX = 0.5f   + wr[112] * 9.5f;
    const float parCFR   =          wr[128] * 0.1f;
    const float parCWH   =          wr[144] * 0.2f;
    const float parC     =          wr[160];
    const float parTR    =          wr[176] * 20.0f;
    const float parAc    =          wr[192] * 2500.0f;

    // ---- regional flow (time-invariant per (g,m)) ----
    const float acm = ac[g];
    float regional_flow;
    {
        const float rf = fminf(fmaxf((acm - parAc) * 0.001f, -1.0f), 1.0f);
        if (acm < 2500.0f) {
            regional_flow = rf * parTR;
        } else {
            const float e = fminf(fmaxf(-(acm - 2500.0f) * (1.0f / 50.0f), -10.0f), 0.0f);
            regional_flow = expf(e) * parTR;
        }
    }

    const float invFC       = 1.0f / parFC;
    const float invLPFC     = 1.0f / (parLP * parFC);
    const float negCFRCFMAX = -(parCFR * parCFMAX);
    const float oneMK1      = 1.0f - parK1;   // SUZ after Q1 = SUZ*(1-K1)
    const float oneMK2      = 1.0f - parK2;   // SLZ after Q2 = SLZ*(1-K2)

    float SNOWPACK = 0.001f, MELTWATER = 0.001f, SM = 0.001f, SUZ = 0.001f, SLZ = 0.001f;

    const float* xb = x + (size_t)g * 3;    // forcing base for this grid
    float* og = out + g;                    // advances NGRID per step

    // ---- preload batch 0 forcing ----
    float Pb[TBATCH], Tb[TBATCH], Eb[TBATCH];
    #pragma unroll
    for (int k = 0; k < TBATCH; ++k) {
        const float* a = xb + (size_t)k * XSTRIDE;
        Pb[k] = __ldg(a + 0);
        Tb[k] = __ldg(a + 1);
        Eb[k] = __ldg(a + 2);
    }

    #pragma unroll 1
    for (int tb = 0; tb < NBATCH; ++tb) {
        // ---- prefetch next batch's forcing (clamped; last batch re-reads itself) ----
        const int tbn = (tb + 1 < NBATCH) ? (tb + 1) : tb;
        const float* xn = xb + (size_t)tbn * TBATCH * XSTRIDE;
        float Pn[TBATCH], Tn[TBATCH], En[TBATCH];
        #pragma unroll
        for (int k = 0; k < TBATCH; ++k) {
            const float* a = xn + (size_t)k * XSTRIDE;
            Pn[k] = __ldg(a + 0);
            Tn[k] = __ldg(a + 1);
            En[k] = __ldg(a + 2);
        }

        float qbuf[TBATCH];

        #pragma unroll
        for (int k = 0; k < TBATCH; ++k) {
            const float Pm   = Pb[k];
            const float Tm   = Tb[k];
            const float PETm = Eb[k];

            // ---- snow routine ----
            const float dtt  = Tm - parTT;
            const float RAIN = (dtt >= 0.0f) ? Pm : 0.0f;
            SNOWPACK += Pm - RAIN;
            const float melt = fminf(fmaxf(parCFMAX * dtt, 0.0f), SNOWPACK);
            MELTWATER += melt;
            SNOWPACK  -= melt;
            const float refreezing = fminf(fmaxf(negCFRCFMAX * dtt, 0.0f), MELTWATER);
            SNOWPACK  += refreezing;
            MELTWATER -= refreezing;
            const float tosoil = fmaxf(MELTWATER - parCWH * SNOWPACK, 0.0f);
            MELTWATER -= tosoil;

            // ---- soil routine ----
            // powf of non-negative base is >= 0 -> lower clip of jnp.clip is dead
            const float soil_wetness = fminf(__powf(SM * invFC, parBETA), 1.0f);
            const float rt = RAIN + tosoil;
            const float recharge = rt * soil_wetness;
            SM += rt - recharge;
            const float excess = fmaxf(SM - parFC, 0.0f);
            SM -= excess;
            const float evapfactor = fminf(__powf(SM * invLPFC, parBETAET), 1.0f);
            // ETact fold: max(SM - min(SM, PET*ef), NZ) == max(SM - PET*ef, NZ)
            SM = fmaxf(SM - PETm * evapfactor, NEARZERO);
            // capillary: parC<=1 and (1-min(SM/FC,1))<=1 -> product <= SLZ, outer min dead
            const float capillary = (parC * SLZ) * (1.0f - fminf(SM * invFC, 1.0f));
            SM  = fmaxf(SM + capillary, NEARZERO);
            SLZ = fmaxf(SLZ - capillary, NEARZERO);

            // ---- response routine ----
            SUZ += recharge + excess;
            const float PERC = fminf(SUZ, parPERC);
            SUZ -= PERC;
            const float Q0 = parK0 * fmaxf(SUZ - parUZL, 0.0f);
            SUZ -= Q0;
            const float Q1 = parK1 * SUZ;
            SUZ *= oneMK1;                       // == SUZ - Q1
            SLZ = fmaxf(SLZ + PERC + regional_flow, 0.0f);
            const float Q2 = parK2 * SLZ;
            SLZ *= oneMK2;                       // == SLZ - Q2
            qbuf[k] = Q0 + Q1 + Q2;
        }

        // 5 independent 16-lane butterfly reductions -> shuffle latency pipelines
        #pragma unroll
        for (int k = 0; k < TBATCH; ++k) {
            float q = qbuf[k];
            q += __shfl_xor_sync(0xffffffffu, q, 8);
            q += __shfl_xor_sync(0xffffffffu, q, 4);
            q += __shfl_xor_sync(0xffffffffu, q, 2);
            q += __shfl_xor_sync(0xffffffffu, q, 1);
            qbuf[k] = q;
        }

        if (m == 0) {
            #pragma unroll
            for (int k = 0; k < TBATCH; ++k)
                og[(size_t)k * NGRID] = qbuf[k] * (1.0f / 16.0f);
        }
        og += (size_t)TBATCH * NGRID;

        // rotate double buffer
        #pragma unroll
        for (int k = 0; k < TBATCH; ++k) {
            Pb[k] = Pn[k];
            Tb[k] = Tn[k];
            Eb[k] = En[k];
        }
    }
}

extern "C" void kernel_launch(void* const* d_in, const int* in_sizes, int n_in,
                              void* d_out, int out_size) {
    const float* x  = nullptr;
    const float* pr = nullptr;
    const float* wr = nullptr;
    const float* ac = nullptr;
    for (int i = 0; i < n_in; ++i) {
        const long n = (long)in_sizes[i];
        if      (n == 365L * NGRID * 3)            x  = (const float*)d_in[i];
        else if (n == 365L * NGRID * 3 * NMUL)     pr = (const float*)d_in[i];
        else if (n == (long)NGRID * 13 * NMUL)     wr = (const float*)d_in[i];
        else if (n == (long)NGRID)                 ac = (const float*)d_in[i];
    }
    // measured-best geometry: one warp per block, 5000 blocks, work-stealing balance
    const int threads = 32;
    const int blocks  = (NGRID * NMUL + threads - 1) / threads;  // 5000
    hbv_waterloss_kernel<<<blocks, threads>>>(x, pr, wr, ac, (float*)d_out);
}

// round 9
// speedup vs baseline: 1.1117x; 1.0183x over previous
#include <cuda_runtime.h>

#define NGRID 10000
#define NSTEP 365
#define NMUL 16
#define NEARZERO 1e-5f
#define TBATCH 5            // 365 = 5 * 73
#define NBATCH (NSTEP / TBATCH)
#define XSTRIDE (NGRID * 3)
#define RSTRIDE 36          // smem row stride (floats): 32 data + 4 pad (bank stagger)

struct Forc { float P[TBATCH], T[TBATCH], E[TBATCH]; };

__device__ __forceinline__ void load_batch(const float* __restrict__ xb, int tb, Forc& f) {
    const float* a = xb + (size_t)tb * TBATCH * XSTRIDE;
    #pragma unroll
    for (int k = 0; k < TBATCH; ++k) {
        f.P[k] = __ldg(a + 0);
        f.T[k] = __ldg(a + 1);
        f.E[k] = __ldg(a + 2);
        a += XSTRIDE;
    }
}

__global__ __launch_bounds__(32)
void hbv_waterloss_kernel(
    const float* __restrict__ x,     // (365, 10000, 3) P,T,PET
    const float* __restrict__ praw,  // (365, 10000, 3, 16) -- only step 364 used
    const float* __restrict__ wraw,  // (10000, 13, 16)
    const float* __restrict__ ac,    // (10000,)
    float* __restrict__ out)         // (365, 10000)
{
    __shared__ float red[2][TBATCH * RSTRIDE];

    const int lane = threadIdx.x;                  // 0..31
    const int tid  = blockIdx.x * 32 + lane;
    const int g = tid >> 4;        // grid cell (lanes 0-15 -> g0, 16-31 -> g0+1)
    const int m = tid & 15;        // multiplier index

    // ---- parameter scaling (HBV params from last timestep: static_idx = -1) ----
    const float* pr = praw + ((size_t)364 * NGRID + g) * (3 * NMUL) + m;
    const float parBETA   = 1.0f  + pr[0]      * 5.0f;
    const float parK0     = 0.05f + pr[16]     * 0.85f;
    const float parBETAET = 0.3f  + pr[32]     * 4.7f;

    const float* wr = wraw + (size_t)g * (13 * NMUL) + m;
    const float parFC    = 50.0f  + wr[0]   * 950.0f;
    const float parK1    = 0.01f  + wr[16]  * 0.49f;
    const float parK2    = 0.001f + wr[32]  * 0.199f;
    const float parLP    = 0.2f   + wr[48]  * 0.8f;
    const float parPERC  =          wr[64]  * 10.0f;
    const float parUZL   =          wr[80]  * 100.0f;
    const float parTT    = -2.5f  + wr[96]  * 5.0f;
    const float parCFMAX = 0.5f   + wr[112] * 9.5f;
    const float parCFR   =          wr[128] * 0.1f;
    const float parCWH   =          wr[144] * 0.2f;
    const float parC     =          wr[160];
    const float parTR    =          wr[176] * 20.0f;
    const float parAc    =          wr[192] * 2500.0f;

    // ---- regional flow (time-invariant per (g,m)) ----
    const float acm = ac[g];
    float regional_flow;
    {
        const float rf = fminf(fmaxf((acm - parAc) * 0.001f, -1.0f), 1.0f);
        if (acm < 2500.0f) {
            regional_flow = rf * parTR;
        } else {
            const float e = fminf(fmaxf(-(acm - 2500.0f) * (1.0f / 50.0f), -10.0f), 0.0f);
            regional_flow = expf(e) * parTR;
        }
    }

    const float invFC       = 1.0f / parFC;
    const float invLPFC     = 1.0f / (parLP * parFC);
    const float negCFRCFMAX = -(parCFR * parCFMAX);
    const float oneMK1      = 1.0f - parK1;
    const float oneMK2      = 1.0f - parK2;

    float SNOWPACK = 0.001f, MELTWATER = 0.001f, SM = 0.001f, SUZ = 0.001f, SLZ = 0.001f;

    const float* xb = x + (size_t)g * 3;            // forcing base for this grid
    float* const outg = out + (size_t)blockIdx.x * 2; // warp's grid pair base (g0 = 2*blockIdx.x)

    // reduction job for this lane: lanes 0..9 -> (step k, half h)
    const int jk = lane >> 1;        // step within batch
    const int jh = lane & 1;         // which grid of the pair
    const bool jactive = (lane < 10);

    // ---- one batch of TBATCH steps (compute + STS), then transpose-reduce ----
    auto do_batch = [&](const Forc& f, int tb, int buf) {
        #pragma unroll
        for (int k = 0; k < TBATCH; ++k) {
            const float Pm   = f.P[k];
            const float Tm   = f.T[k];
            const float PETm = f.E[k];

            // ---- snow routine ----
            const float dtt  = Tm - parTT;
            const float RAIN = (dtt >= 0.0f) ? Pm : 0.0f;
            SNOWPACK += Pm - RAIN;
            const float melt = fminf(fmaxf(parCFMAX * dtt, 0.0f), SNOWPACK);
            MELTWATER += melt;
            SNOWPACK  -= melt;
            const float refreezing = fminf(fmaxf(negCFRCFMAX * dtt, 0.0f), MELTWATER);
            SNOWPACK  += refreezing;
            MELTWATER -= refreezing;
            const float tosoil = fmaxf(MELTWATER - parCWH * SNOWPACK, 0.0f);
            MELTWATER -= tosoil;

            // ---- soil routine ----
            const float soil_wetness = fminf(__powf(SM * invFC, parBETA), 1.0f);
            const float rt = RAIN + tosoil;
            const float recharge = rt * soil_wetness;
            SM += rt - recharge;
            const float excess = fmaxf(SM - parFC, 0.0f);
            SM -= excess;
            const float evapfactor = fminf(__powf(SM * invLPFC, parBETAET), 1.0f);
            SM = fmaxf(SM - PETm * evapfactor, NEARZERO);
            const float capillary = (parC * SLZ) * (1.0f - fminf(SM * invFC, 1.0f));
            SM  = fmaxf(SM + capillary, NEARZERO);
            SLZ = fmaxf(SLZ - capillary, NEARZERO);

            // ---- response routine ----
            SUZ += recharge + excess;
            const float PERC = fminf(SUZ, parPERC);
            SUZ -= PERC;
            const float Q0 = parK0 * fmaxf(SUZ - parUZL, 0.0f);
            SUZ -= Q0;
            const float Q1 = parK1 * SUZ;
            SUZ *= oneMK1;
            SLZ = fmaxf(SLZ + PERC + regional_flow, 0.0f);
            const float Q2 = parK2 * SLZ;
            SLZ *= oneMK2;

            red[buf][k * RSTRIDE + lane] = Q0 + Q1 + Q2;
        }

        __syncthreads();   // single-warp BAR (~3 cyc), drains STS

        // lanes 0..9: each sums one (step, grid-half) row of 16 floats
        if (jactive) {
            const float4* p = reinterpret_cast<const float4*>(
                &red[buf][jk * RSTRIDE + jh * 16]);
            const float4 a = p[0], b = p[1], c = p[2], d = p[3];
            const float4 s0 = make_float4(a.x + b.x, a.y + b.y, a.z + b.z, a.w + b.w);
            const float4 s1 = make_float4(c.x + d.x, c.y + d.y, c.z + d.z, c.w + d.w);
            const float sum = ((s0.x + s1.x) + (s0.y + s1.y))
                            + ((s0.z + s1.z) + (s0.w + s1.w));
            outg[((size_t)tb * TBATCH + jk) * NGRID + jh] = sum * (1.0f / 16.0f);
        }
    };

    // ---- software-pipelined main loop with ping-pong forcing buffers ----
    Forc A, B;
    load_batch(xb, 0, A);
    load_batch(xb, 1, B);

    #pragma unroll 1
    for (int tb = 0; tb < NBATCH - 1; tb += 2) {
        do_batch(A, tb, 0);
        load_batch(xb, tb + 2, A);                       // tb+2 <= 72, always valid
        do_batch(B, tb + 1, 1);
        const int nb = (tb + 3 <= NBATCH - 1) ? (tb + 3) : (NBATCH - 1);
        load_batch(xb, nb, B);                           // clamped (last iter redundant)
    }
    do_batch(A, NBATCH - 1, 0);                          // batch 72, loaded at tb=70
}

extern "C" void kernel_launch(void* const* d_in, const int* in_sizes, int n_in,
                              void* d_out, int out_size) {
    const float* x  = nullptr;
    const float* pr = nullptr;
    const float* wr = nullptr;
    const float* ac = nullptr;
    for (int i = 0; i < n_in; ++i) {
        const long n = (long)in_sizes[i];
        if      (n == 365L * NGRID * 3)            x  = (const float*)d_in[i];
        else if (n == 365L * NGRID * 3 * NMUL)     pr = (const float*)d_in[i];
        else if (n == (long)NGRID * 13 * NMUL)     wr = (const float*)d_in[i];
        else if (n == (long)NGRID)                 ac = (const float*)d_in[i];
    }
    // measured-best geometry: one warp per block, 5000 blocks (covers 160000 threads exactly)
    hbv_waterloss_kernel<<<5000, 32>>>(x, pr, wr, ac, (float*)d_out);
}